// round 13
// baseline (speedup 1.0000x reference)
#include <cuda_runtime.h>
#include <cuda_bf16.h>
#include <math.h>

#define NA 16384
#define NE 262144
#define DD 128
#define FF 128
#define GG 50
#define NL 4
#define NMOL 32
#define TT 4096
#define DMAX 1.7320509f
#define AP 132

// ---------------- scratch ----------------------------------------------------
__device__ __align__(16) float g_h[NA * DD];
__device__ __align__(16) float g_t[NA * DD];
__device__ __align__(16) float g_agg[NA * DD];
__device__ __align__(16) float g_r[NA * 64];
__device__ __align__(16) float g_R[TT * 64];
__device__ __align__(16) float g_Cd[TT];
__device__ __align__(16) float g_ttmp[NL * TT * FF];
__device__ __align__(16) float g_tab[NL * TT * FF];
__device__ __align__(16) float g_W1p[NL * 64 * FF];
__device__ __align__(16) float g_zero[DD];
__device__ float g_dist[NE];
__device__ int   g_cnt[NA];
__device__ int   g_off[NA + 1];
__device__ int   g_cur[NA];
__device__ __align__(16) int2 g_pk[NE];

__device__ __forceinline__ float sspf(float x) {
    float sp = fmaxf(x, 0.0f) + log1pf(expf(-fabsf(x)));
    return sp - 0.69314718055994530942f;
}

// split two fp32 into packed bf16x2 hi + lo (Markidis split, no scaling needed)
__device__ __forceinline__ void split2(float x0, float x1, unsigned& hi, unsigned& lo) {
    __nv_bfloat162 h = __floats2bfloat162_rn(x0, x1);
    float r0 = x0 - __bfloat162float(h.x);
    float r1 = x1 - __bfloat162float(h.y);
    __nv_bfloat162 l = __floats2bfloat162_rn(r0, r1);
    hi = *(unsigned*)&h;
    lo = *(unsigned*)&l;
}

#define MMA_BF16(d, a, b)                                                     \
    asm volatile(                                                             \
        "mma.sync.aligned.m16n8k16.row.col.f32.bf16.bf16.f32 "               \
        "{%0,%1,%2,%3},{%4,%5,%6,%7},{%8,%9},{%0,%1,%2,%3};"                 \
        : "+f"(d[0]), "+f"(d[1]), "+f"(d[2]), "+f"(d[3])                      \
        : "r"(a[0]), "r"(a[1]), "r"(a[2]), "r"(a[3]), "r"(b[0]), "r"(b[1]))

// ---------------- merged prep kernel -----------------------------------------
__global__ void k_prep(const float* __restrict__ z, const float* __restrict__ embW,
                       const float* __restrict__ embB, const float* __restrict__ pos,
                       const int* __restrict__ src, const int* __restrict__ dst,
                       const float* __restrict__ W1) {
    int i = blockIdx.x * blockDim.x + threadIdx.x;
    // embed: h = z @ embW + embB
    {
        int n = i >> 7, d = i & 127;
        g_h[i] = z[n] * embW[d] + embB[d];
    }
    if (i < NE) {  // geometry + dst histogram
        int s = src[i], d = dst[i];
        float dx = pos[3 * s + 0] - pos[3 * d + 0];
        float dy = pos[3 * s + 1] - pos[3 * d + 1];
        float dz = pos[3 * s + 2] - pos[3 * d + 2];
        g_dist[i] = sqrtf(dx * dx + dy * dy + dz * dz + 1e-12f);
        atomicAdd(&g_cnt[d], 1);
    }
    if (i < TT * 64) {  // RBF matrix + cutoff
        int row = i >> 6, g = i & 63;
        float d = row * (DMAX / (TT - 1));
        float mu = g * (5.0f / 49.0f);
        float t = d - mu;
        g_R[i] = (g < GG) ? expf(-4.0f * t * t) : 0.0f;
        if (g == 0)
            g_Cd[row] = 0.5f * (cosf(d * 0.62831853071795864769f) + 1.0f);
    }
    if (i < NL * 64 * FF) {  // zero-padded W1
        int l = i / (64 * FF);
        int rem = i - l * (64 * FF);
        int g = rem >> 7, f = rem & 127;
        g_W1p[i] = (g < GG) ? W1[(l * GG + g) * FF + f] : 0.0f;
    }
    if (i < DD) g_zero[i] = 0.0f;
}

// ---------------- CSR scan (also zeroes out) ----------------------------------
__global__ void __launch_bounds__(1024) k_scan(float* __restrict__ out) {
    __shared__ int part[1024];
    int t = threadIdx.x;
    if (t < NMOL) out[t] = 0.0f;
    int base = t * 16;
    int loc[16];
    int s = 0;
#pragma unroll
    for (int i = 0; i < 16; i++) { loc[i] = s; s += g_cnt[base + i]; }
    part[t] = s;
    __syncthreads();
    for (int off = 1; off < 1024; off <<= 1) {
        int v = (t >= off) ? part[t - off] : 0;
        __syncthreads();
        part[t] += v;
        __syncthreads();
    }
    int excl = (t > 0) ? part[t - 1] : 0;
#pragma unroll
    for (int i = 0; i < 16; i++) {
        g_off[base + i] = excl + loc[i];
        g_cur[base + i] = excl + loc[i];
    }
    if (t == 1023) g_off[NA] = excl + s;
}

__global__ void k_fill(const int* __restrict__ src, const int* __restrict__ dst) {
    int e = blockIdx.x * blockDim.x + threadIdx.x;
    if (e >= NE) return;
    int p = atomicAdd(&g_cur[dst[e]], 1);
    float x = g_dist[e] * ((TT - 1) / DMAX);
    g_pk[p] = make_int2(src[e], __float_as_int(x));
}

// ---------------- edge gather ------------------------------------------------
__global__ void __launch_bounds__(256) k_gather(const float* __restrict__ tab) {
    int n = blockIdx.x * 8 + (threadIdx.x >> 5);
    int lane = threadIdx.x & 31;
    int beg = g_off[n], end = g_off[n + 1];
    float ax = 0.f, ay = 0.f, az = 0.f, aw = 0.f;
    int c4 = lane << 2;
    int i = beg;
    for (; i + 1 < end; i += 2) {
        int2 pA = g_pk[i];
        int2 pB = g_pk[i + 1];
        float xA = __int_as_float(pA.y);
        float xB = __int_as_float(pB.y);
        int iA = min((int)xA, TT - 2);
        int iB = min((int)xB, TT - 2);
        float wA = xA - (float)iA;
        float wB = xB - (float)iB;
        const float4 a0 = *(const float4*)&tab[(size_t)iA * FF + c4];
        const float4 a1 = *(const float4*)&tab[(size_t)(iA + 1) * FF + c4];
        const float4 b0 = *(const float4*)&tab[(size_t)iB * FF + c4];
        const float4 b1 = *(const float4*)&tab[(size_t)(iB + 1) * FF + c4];
        const float4 ta = *(const float4*)&g_t[(size_t)pA.x * DD + c4];
        const float4 tb = *(const float4*)&g_t[(size_t)pB.x * DD + c4];
        ax = fmaf(fmaf(wA, a1.x - a0.x, a0.x), ta.x, ax);
        ay = fmaf(fmaf(wA, a1.y - a0.y, a0.y), ta.y, ay);
        az = fmaf(fmaf(wA, a1.z - a0.z, a0.z), ta.z, az);
        aw = fmaf(fmaf(wA, a1.w - a0.w, a0.w), ta.w, aw);
        ax = fmaf(fmaf(wB, b1.x - b0.x, b0.x), tb.x, ax);
        ay = fmaf(fmaf(wB, b1.y - b0.y, b0.y), tb.y, ay);
        az = fmaf(fmaf(wB, b1.z - b0.z, b0.z), tb.z, az);
        aw = fmaf(fmaf(wB, b1.w - b0.w, b0.w), tb.w, aw);
    }
    if (i < end) {
        int2 pA = g_pk[i];
        float xA = __int_as_float(pA.y);
        int iA = min((int)xA, TT - 2);
        float wA = xA - (float)iA;
        const float4 a0 = *(const float4*)&tab[(size_t)iA * FF + c4];
        const float4 a1 = *(const float4*)&tab[(size_t)(iA + 1) * FF + c4];
        const float4 ta = *(const float4*)&g_t[(size_t)pA.x * DD + c4];
        ax = fmaf(fmaf(wA, a1.x - a0.x, a0.x), ta.x, ax);
        ay = fmaf(fmaf(wA, a1.y - a0.y, a0.y), ta.y, ay);
        az = fmaf(fmaf(wA, a1.z - a0.z, a0.z), ta.z, az);
        aw = fmaf(fmaf(wA, a1.w - a0.w, a0.w), ta.w, aw);
    }
    float4 o; o.x = ax; o.y = ay; o.z = az; o.w = aw;
    *(float4*)&g_agg[(size_t)n * DD + c4] = o;
}

// ---------------- bf16x3 stage GEMM (smem A fp32, global B fp32) -------------
// acc = A[64][K=128](smem, stride AP) @ B[128][BN]; m16n8k16 bf16 mma, 3-term
// split (hi*hi + lo*hi + hi*lo). C-fragment layout identical to m16n8k8.
template <int BN, int K>
__device__ __forceinline__ void stage_gemm(
    const float* __restrict__ Asm, const float* __restrict__ Bg,
    float* __restrict__ Bs, int tid, float (&acc)[2][BN / 32][4]) {
    constexpr int BNP = BN + 4;
    constexpr int NCH = K / 32;
    constexpr int WN = BN / 4;
    constexpr int NT = BN / 32;
    int wid = tid >> 5, lane = tid & 31;
    int wm = wid & 1, wn = wid >> 1;
    int grp = lane >> 2, t4 = lane & 3;

    auto ldchunk = [&](int c, int buf) {
#pragma unroll
        for (int it = 0; it < (32 * BN / 4) / 256; it++) {
            int idx = tid + it * 256;
            int k = idx / (BN / 4), nq = idx % (BN / 4);
            const float4* gp = (const float4*)(Bg + (size_t)(c * 32 + k) * BN) + nq;
            float* sp = &Bs[(buf * 32 + k) * BNP + nq * 4];
            unsigned sa = (unsigned)__cvta_generic_to_shared(sp);
            asm volatile("cp.async.cg.shared.global [%0], [%1], 16;" :: "r"(sa), "l"(gp));
        }
        asm volatile("cp.async.commit_group;");
    };

    ldchunk(0, 0);
    asm volatile("cp.async.wait_group 0;");
    __syncthreads();

#pragma unroll
    for (int im = 0; im < 2; im++)
#pragma unroll
        for (int in = 0; in < NT; in++)
#pragma unroll
            for (int q = 0; q < 4; q++) acc[im][in][q] = 0.0f;

    for (int c = 0; c < NCH; c++) {
        int buf = c & 1;
        if (c + 1 < NCH) ldchunk(c + 1, buf ^ 1);
#pragma unroll
        for (int kk = 0; kk < 2; kk++) {          // two k16 steps per 32-chunk
            int k0 = c * 32 + kk * 16;
            int kb = kk * 16;
            unsigned ah[2][4], al[2][4];
#pragma unroll
            for (int im = 0; im < 2; im++) {
                int rb = wm * 32 + im * 16 + grp;
                float2 p00 = *(const float2*)&Asm[rb * AP + k0 + 2 * t4];
                float2 p10 = *(const float2*)&Asm[(rb + 8) * AP + k0 + 2 * t4];
                float2 p01 = *(const float2*)&Asm[rb * AP + k0 + 2 * t4 + 8];
                float2 p11 = *(const float2*)&Asm[(rb + 8) * AP + k0 + 2 * t4 + 8];
                split2(p00.x, p00.y, ah[im][0], al[im][0]);
                split2(p10.x, p10.y, ah[im][1], al[im][1]);
                split2(p01.x, p01.y, ah[im][2], al[im][2]);
                split2(p11.x, p11.y, ah[im][3], al[im][3]);
            }
            unsigned bh[NT][2], bl[NT][2];
#pragma unroll
            for (int in = 0; in < NT; in++) {
                int nb = wn * WN + in * 8 + grp;
                float y0 = Bs[(buf * 32 + kb + 2 * t4) * BNP + nb];
                float y1 = Bs[(buf * 32 + kb + 2 * t4 + 1) * BNP + nb];
                float y2 = Bs[(buf * 32 + kb + 2 * t4 + 8) * BNP + nb];
                float y3 = Bs[(buf * 32 + kb + 2 * t4 + 9) * BNP + nb];
                split2(y0, y1, bh[in][0], bl[in][0]);
                split2(y2, y3, bh[in][1], bl[in][1]);
            }
#pragma unroll
            for (int im = 0; im < 2; im++)
#pragma unroll
                for (int in = 0; in < NT; in++) {
                    float* d = acc[im][in];
                    MMA_BF16(d, al[im], bh[in]);
                    MMA_BF16(d, ah[im], bl[in]);
                    MMA_BF16(d, ah[im], bh[in]);
                }
        }
        if (c + 1 < NCH) {
            asm volatile("cp.async.wait_group 0;");
            __syncthreads();
        }
    }
}

// ---------------- fused layer kernel -----------------------------------------
template <int BN3, bool SSP3>
__global__ void __launch_bounds__(256)
k_layer(const float* __restrict__ cf2W, const float* __restrict__ cf2b,
        const float* __restrict__ ilW, const float* __restrict__ ilb,
        const float* __restrict__ W3, const float* __restrict__ b3,
        float* __restrict__ out3) {
    extern __shared__ float sm[];
    float* A0 = sm;
    float* A1 = sm + 64 * AP;
    float* Bs = sm + 2 * 64 * AP;

    int tid = threadIdx.x;
    int m0 = blockIdx.x * 64;
    int wid = tid >> 5, lane = tid & 31;
    int wm = wid & 1, wn = wid >> 1;
    int grp = lane >> 2, t4 = lane & 3;

    for (int idx = tid; idx < 64 * 32; idx += 256) {
        int r = idx >> 5, c4 = idx & 31;
        *(float4*)&A0[r * AP + c4 * 4] =
            *(const float4*)&g_agg[(size_t)(m0 + r) * DD + c4 * 4];
    }
    __syncthreads();

    float acc[2][4][4];

    // ---- stage 1: u = ssp(agg @ cf2 + cf2b) -> A1 ----
    stage_gemm<128, 128>(A0, cf2W, Bs, tid, acc);
#pragma unroll
    for (int im = 0; im < 2; im++) {
        int rb = wm * 32 + im * 16 + grp;
#pragma unroll
        for (int in = 0; in < 4; in++) {
            int col = wn * 32 + in * 8 + 2 * t4;
            float b0 = cf2b[col], b1 = cf2b[col + 1];
#pragma unroll
            for (int hr = 0; hr < 2; hr++) {
                int r = rb + hr * 8;
                float2 v;
                v.x = sspf(acc[im][in][hr * 2 + 0] + b0);
                v.y = sspf(acc[im][in][hr * 2 + 1] + b1);
                *(float2*)&A1[r * AP + col] = v;
            }
        }
    }
    __syncthreads();

    // ---- stage 2: h += u @ ilW + ilb -> global + A0 ----
    stage_gemm<128, 128>(A1, ilW, Bs, tid, acc);
#pragma unroll
    for (int im = 0; im < 2; im++) {
        int rb = wm * 32 + im * 16 + grp;
#pragma unroll
        for (int in = 0; in < 4; in++) {
            int col = wn * 32 + in * 8 + 2 * t4;
            float b0 = ilb[col], b1 = ilb[col + 1];
#pragma unroll
            for (int hr = 0; hr < 2; hr++) {
                int r = rb + hr * 8;
                float* hp = &g_h[(size_t)(m0 + r) * DD + col];
                float2 hv = *(const float2*)hp;
                float2 v;
                v.x = acc[im][in][hr * 2 + 0] + b0 + hv.x;
                v.y = acc[im][in][hr * 2 + 1] + b1 + hv.y;
                *(float2*)hp = v;
                *(float2*)&A0[r * AP + col] = v;
            }
        }
    }
    __syncthreads();

    // ---- stage 3: out3 = epi3(h @ W3 + b3) ----
    float acc3[2][BN3 / 32][4];
    stage_gemm<BN3, 128>(A0, W3, Bs, tid, acc3);
    constexpr int WN3 = BN3 / 4;
#pragma unroll
    for (int im = 0; im < 2; im++) {
        int rb = wm * 32 + im * 16 + grp;
#pragma unroll
        for (int in = 0; in < BN3 / 32; in++) {
            int col = wn * WN3 + in * 8 + 2 * t4;
            float b0 = b3[col], b1 = b3[col + 1];
#pragma unroll
            for (int hr = 0; hr < 2; hr++) {
                int r = m0 + rb + hr * 8;
                float x0 = acc3[im][in][hr * 2 + 0] + b0;
                float x1 = acc3[im][in][hr * 2 + 1] + b1;
                if (SSP3) { x0 = sspf(x0); x1 = sspf(x1); }
                float2 v; v.x = x0; v.y = x1;
                *(float2*)&out3[(size_t)r * BN3 + col] = v;
            }
        }
    }
}

// ---------------- standalone bf16x3 GEMM (tables + t0) ------------------------
// EPI: 0 none, 1 ssp, 2 bias-then-*scale[m].
template <int BN, int K, int EPI>
__global__ void __launch_bounds__(256)
k_gemm3(const float* __restrict__ A, const float* __restrict__ B,
        const float* __restrict__ bias, const float* __restrict__ scale,
        float* __restrict__ C, int sA, int sB, int sBias, int sC) {
    extern __shared__ float sm[];
    float* As = sm;
    float* Bs = sm + 64 * AP;

    A += (size_t)blockIdx.y * sA;
    B += (size_t)blockIdx.y * sB;
    if (bias) bias += (size_t)blockIdx.y * sBias;
    C += (size_t)blockIdx.y * sC;

    int tid = threadIdx.x;
    int m0 = blockIdx.x * 64;
    int wid = tid >> 5, lane = tid & 31;
    int wm = wid & 1, wn = wid >> 1;
    int grp = lane >> 2, t4 = lane & 3;

    for (int idx = tid; idx < 64 * (K / 4); idx += 256) {
        int r = idx / (K / 4), c4 = idx % (K / 4);
        *(float4*)&As[r * AP + c4 * 4] =
            *(const float4*)&A[(size_t)(m0 + r) * K + c4 * 4];
    }
    __syncthreads();

    float acc[2][BN / 32][4];
    stage_gemm<BN, K>(As, B, Bs, tid, acc);

    constexpr int WN = BN / 4;
#pragma unroll
    for (int im = 0; im < 2; im++) {
        int rbase = m0 + wm * 32 + im * 16 + grp;
#pragma unroll
        for (int in = 0; in < BN / 32; in++) {
            int col = wn * WN + in * 8 + 2 * t4;
            float b0 = bias ? bias[col] : 0.f;
            float b1 = bias ? bias[col + 1] : 0.f;
#pragma unroll
            for (int hr = 0; hr < 2; hr++) {
                int r = rbase + hr * 8;
                float x0 = acc[im][in][hr * 2 + 0] + b0;
                float x1 = acc[im][in][hr * 2 + 1] + b1;
                if (EPI == 1) { x0 = sspf(x0); x1 = sspf(x1); }
                if (EPI == 2) { float sc = scale[r]; x0 *= sc; x1 *= sc; }
                float2 v; v.x = x0; v.y = x1;
                *(float2*)&C[(size_t)r * BN + col] = v;
            }
        }
    }
}

// ---------------- readout ----------------------------------------------------
__global__ void k_readout(const int* __restrict__ batch, const float* __restrict__ w,
                          const float* __restrict__ b, float* __restrict__ out) {
    int gw = (blockIdx.x * blockDim.x + threadIdx.x) >> 5;
    int lane = threadIdx.x & 31;
    if (gw >= NA) return;
    float v = g_r[gw * 64 + lane] * w[lane] + g_r[gw * 64 + lane + 32] * w[lane + 32];
#pragma unroll
    for (int o = 16; o > 0; o >>= 1) v += __shfl_down_sync(0xFFFFFFFFu, v, o);
    if (lane == 0) atomicAdd(&out[batch[gw]], v + b[0]);
}

// ---------------- launch -----------------------------------------------------
extern "C" void kernel_launch(void* const* d_in, const int* in_sizes, int n_in,
                              void* d_out, int out_size) {
    const float* z    = (const float*)d_in[0];
    const float* pos  = (const float*)d_in[1];
    const int*   bat  = (const int*)d_in[2];
    const int*   esrc = (const int*)d_in[3];
    const int*   edst = (const int*)d_in[4];
    const float* embW = (const float*)d_in[5];
    const float* embB = (const float*)d_in[6];
    const float* W1   = (const float*)d_in[7];
    const float* b1   = (const float*)d_in[8];
    const float* W2   = (const float*)d_in[9];
    const float* b2   = (const float*)d_in[10];
    const float* cf1  = (const float*)d_in[11];
    const float* cf2  = (const float*)d_in[12];
    const float* cf2b = (const float*)d_in[13];
    const float* ilW  = (const float*)d_in[14];
    const float* ilb  = (const float*)d_in[15];
    const float* l1W  = (const float*)d_in[16];
    const float* l1b  = (const float*)d_in[17];
    const float* l2W  = (const float*)d_in[18];
    const float* l2b  = (const float*)d_in[19];
    float* out = (float*)d_out;

    float *p_h, *p_t, *p_r, *p_R, *p_Cd, *p_ttmp, *p_tab, *p_W1p, *p_zero;
    int *p_cnt;
    cudaGetSymbolAddress((void**)&p_h, g_h);
    cudaGetSymbolAddress((void**)&p_t, g_t);
    cudaGetSymbolAddress((void**)&p_r, g_r);
    cudaGetSymbolAddress((void**)&p_R, g_R);
    cudaGetSymbolAddress((void**)&p_Cd, g_Cd);
    cudaGetSymbolAddress((void**)&p_ttmp, g_ttmp);
    cudaGetSymbolAddress((void**)&p_tab, g_tab);
    cudaGetSymbolAddress((void**)&p_W1p, g_W1p);
    cudaGetSymbolAddress((void**)&p_zero, g_zero);
    cudaGetSymbolAddress((void**)&p_cnt, g_cnt);

    const int SM_G = (64 * AP + 2 * 32 * 132) * 4;
    const int SM_L = (2 * 64 * AP + 2 * 32 * 132) * 4;
    cudaFuncSetAttribute((const void*)k_gemm3<128, 128, 0>,
                         cudaFuncAttributeMaxDynamicSharedMemorySize, SM_G);
    cudaFuncSetAttribute((const void*)k_gemm3<128, 128, 2>,
                         cudaFuncAttributeMaxDynamicSharedMemorySize, SM_G);
    cudaFuncSetAttribute((const void*)k_gemm3<128, 64, 1>,
                         cudaFuncAttributeMaxDynamicSharedMemorySize, SM_G);
    cudaFuncSetAttribute((const void*)k_layer<128, false>,
                         cudaFuncAttributeMaxDynamicSharedMemorySize, SM_L);
    cudaFuncSetAttribute((const void*)k_layer<64, true>,
                         cudaFuncAttributeMaxDynamicSharedMemorySize, SM_L);

    // ---- prep (merged) -------------------------------------------------------
    cudaMemsetAsync(p_cnt, 0, NA * sizeof(int));
    k_prep<<<NA * DD / 256, 256>>>(z, embW, embB, pos, esrc, edst, W1);
    k_scan<<<1, 1024>>>(out);
    k_fill<<<NE / 256, 256>>>(esrc, edst);

    // ---- Wf tables -----------------------------------------------------------
    {
        dim3 g1(TT / 64, NL);
        k_gemm3<128, 64, 1><<<g1, 256, SM_G>>>(
            p_R, p_W1p, b1, nullptr, p_ttmp, 0, 64 * FF, FF, TT * FF);
        k_gemm3<128, 128, 2><<<g1, 256, SM_G>>>(
            p_ttmp, W2, b2, p_Cd, p_tab, TT * FF, FF * FF, FF, TT * FF);
    }

    // ---- t for layer 0 -------------------------------------------------------
    k_gemm3<128, 128, 0><<<NA / 64, 256, SM_G>>>(
        p_h, cf1, nullptr, nullptr, p_t, 0, 0, 0, 0);

    // ---- interaction layers (fused) -------------------------------------------
    for (int l = 0; l < NL; l++) {
        k_gather<<<NA / 8, 256>>>(p_tab + (size_t)l * TT * FF);
        if (l < NL - 1) {
            k_layer<128, false><<<NA / 64, 256, SM_L>>>(
                cf2 + (size_t)l * FF * DD, cf2b + (size_t)l * DD,
                ilW + (size_t)l * DD * DD, ilb + (size_t)l * DD,
                cf1 + (size_t)(l + 1) * DD * FF, p_zero, p_t);
        } else {
            k_layer<64, true><<<NA / 64, 256, SM_L>>>(
                cf2 + (size_t)l * FF * DD, cf2b + (size_t)l * DD,
                ilW + (size_t)l * DD * DD, ilb + (size_t)l * DD,
                l1W, l1b, p_r);
        }
    }

    // ---- readout ---------------------------------------------------------------
    k_readout<<<(NA * 32 + 255) / 256, 256>>>(bat, l2W, l2b, out);
}

// round 15
// speedup vs baseline: 1.0362x; 1.0362x over previous
#include <cuda_runtime.h>
#include <cuda_bf16.h>
#include <math.h>

#define NA 16384
#define NE 262144
#define DD 128
#define FF 128
#define GG 50
#define NL 4
#define NMOL 32
#define TT 4096
#define DMAX 1.7320509f

#define OFF_W1  0
#define OFF_W2  16384
#define OFF_CF1 49152
#define OFF_CF2 81920
#define OFF_IL  114688
#define OFF_L1  147456
#define TOTW    151552

// ---------------- scratch ----------------------------------------------------
__device__ __align__(16) float g_h[NA * DD];
__device__ __align__(16) float g_t[NA * DD];
__device__ __align__(16) float g_agg[NA * DD];
__device__ __align__(16) float g_r[NA * 64];
__device__ __align__(16) float g_R[TT * 64];
__device__ __align__(16) float g_Cd[TT];
__device__ __align__(16) float g_ttmp[NL * TT * FF];
__device__ __align__(16) float g_tab[NL * TT * FF];
__device__ __align__(16) float g_W1p[NL * 64 * FF];
__device__ __align__(16) float g_zero[DD];
__device__ __align__(16) unsigned g_Wh[TOTW];
__device__ __align__(16) unsigned g_Wl[TOTW];
__device__ float g_dist[NE];
__device__ int   g_cnt[NA];
__device__ int   g_off[NA + 1];
__device__ int   g_cur[NA];
__device__ __align__(16) int2 g_pk[NE];

__device__ __forceinline__ float sspf(float x) {
    float sp = fmaxf(x, 0.0f) + log1pf(expf(-fabsf(x)));
    return sp - 0.69314718055994530942f;
}

__device__ __forceinline__ void split2(float x0, float x1, unsigned& hi, unsigned& lo) {
    __nv_bfloat162 h = __floats2bfloat162_rn(x0, x1);
    float r0 = x0 - __bfloat162float(h.x);
    float r1 = x1 - __bfloat162float(h.y);
    __nv_bfloat162 l = __floats2bfloat162_rn(r0, r1);
    hi = *(unsigned*)&h;
    lo = *(unsigned*)&l;
}

#define MMA_BF16(d, a, b)                                                     \
    asm volatile(                                                             \
        "mma.sync.aligned.m16n8k16.row.col.f32.bf16.bf16.f32 "               \
        "{%0,%1,%2,%3},{%4,%5,%6,%7},{%8,%9},{%0,%1,%2,%3};"                 \
        : "+f"(d[0]), "+f"(d[1]), "+f"(d[2]), "+f"(d[3])                      \
        : "r"(a[0]), "r"(a[1]), "r"(a[2]), "r"(a[3]), "r"(b[0]), "r"(b[1]))

// ---------------- merged prep kernel -----------------------------------------
__global__ void k_prep(const float* __restrict__ z, const float* __restrict__ embW,
                       const float* __restrict__ embB, const float* __restrict__ pos,
                       const int* __restrict__ src, const int* __restrict__ dst,
                       const float* __restrict__ W1) {
    int i = blockIdx.x * blockDim.x + threadIdx.x;
    {
        int n = i >> 7, d = i & 127;
        g_h[i] = z[n] * embW[d] + embB[d];
    }
    if (i < NE) {
        int s = src[i], d = dst[i];
        float dx = pos[3 * s + 0] - pos[3 * d + 0];
        float dy = pos[3 * s + 1] - pos[3 * d + 1];
        float dz = pos[3 * s + 2] - pos[3 * d + 2];
        g_dist[i] = sqrtf(dx * dx + dy * dy + dz * dz + 1e-12f);
        atomicAdd(&g_cnt[d], 1);
    }
    if (i < TT * 64) {
        int row = i >> 6, g = i & 63;
        float d = row * (DMAX / (TT - 1));
        float mu = g * (5.0f / 49.0f);
        float t = d - mu;
        g_R[i] = (g < GG) ? expf(-4.0f * t * t) : 0.0f;
        if (g == 0)
            g_Cd[row] = 0.5f * (cosf(d * 0.62831853071795864769f) + 1.0f);
    }
    if (i < NL * 64 * FF) {
        int l = i / (64 * FF);
        int rem = i - l * (64 * FF);
        int g = rem >> 7, f = rem & 127;
        g_W1p[i] = (g < GG) ? W1[(l * GG + g) * FF + f] : 0.0f;
    }
    if (i < DD) g_zero[i] = 0.0f;
}

// ---------------- weight pre-split: fp32 [K][N] -> packed bf16 hi/lo [N][K/2] -
__global__ void k_split(const float* __restrict__ W2, const float* __restrict__ cf1,
                        const float* __restrict__ cf2, const float* __restrict__ ilW,
                        const float* __restrict__ l1W) {
    int i = blockIdx.x * blockDim.x + threadIdx.x;
    if (i >= TOTW) return;
    float x0, x1;
    if (i < OFF_W2) {
        int l = i >> 12, rem = i & 4095, n = rem >> 5, k2 = rem & 31;
        const float* s = g_W1p + l * 64 * 128;
        x0 = s[(2 * k2) * 128 + n]; x1 = s[(2 * k2 + 1) * 128 + n];
    } else if (i < OFF_CF1) {
        int j = i - OFF_W2, l = j >> 13, rem = j & 8191, n = rem >> 6, k2 = rem & 63;
        const float* s = W2 + l * 16384;
        x0 = s[(2 * k2) * 128 + n]; x1 = s[(2 * k2 + 1) * 128 + n];
    } else if (i < OFF_CF2) {
        int j = i - OFF_CF1, l = j >> 13, rem = j & 8191, n = rem >> 6, k2 = rem & 63;
        const float* s = cf1 + l * 16384;
        x0 = s[(2 * k2) * 128 + n]; x1 = s[(2 * k2 + 1) * 128 + n];
    } else if (i < OFF_IL) {
        int j = i - OFF_CF2, l = j >> 13, rem = j & 8191, n = rem >> 6, k2 = rem & 63;
        const float* s = cf2 + l * 16384;
        x0 = s[(2 * k2) * 128 + n]; x1 = s[(2 * k2 + 1) * 128 + n];
    } else if (i < OFF_L1) {
        int j = i - OFF_IL, l = j >> 13, rem = j & 8191, n = rem >> 6, k2 = rem & 63;
        const float* s = ilW + l * 16384;
        x0 = s[(2 * k2) * 128 + n]; x1 = s[(2 * k2 + 1) * 128 + n];
    } else {
        int j = i - OFF_L1, n = j >> 6, k2 = j & 63;
        x0 = l1W[(2 * k2) * 64 + n]; x1 = l1W[(2 * k2 + 1) * 64 + n];
    }
    unsigned h, l_;
    split2(x0, x1, h, l_);
    g_Wh[i] = h;
    g_Wl[i] = l_;
}

// ---------------- CSR scan (also zeroes out) ----------------------------------
__global__ void __launch_bounds__(1024) k_scan(float* __restrict__ out) {
    __shared__ int part[1024];
    int t = threadIdx.x;
    if (t < NMOL) out[t] = 0.0f;
    int base = t * 16;
    int loc[16];
    int s = 0;
#pragma unroll
    for (int i = 0; i < 16; i++) { loc[i] = s; s += g_cnt[base + i]; }
    part[t] = s;
    __syncthreads();
    for (int off = 1; off < 1024; off <<= 1) {
        int v = (t >= off) ? part[t - off] : 0;
        __syncthreads();
        part[t] += v;
        __syncthreads();
    }
    int excl = (t > 0) ? part[t - 1] : 0;
#pragma unroll
    for (int i = 0; i < 16; i++) {
        g_off[base + i] = excl + loc[i];
        g_cur[base + i] = excl + loc[i];
    }
    if (t == 1023) g_off[NA] = excl + s;
}

__global__ void k_fill(const int* __restrict__ src, const int* __restrict__ dst) {
    int e = blockIdx.x * blockDim.x + threadIdx.x;
    if (e >= NE) return;
    int p = atomicAdd(&g_cur[dst[e]], 1);
    float x = g_dist[e] * ((TT - 1) / DMAX);
    g_pk[p] = make_int2(src[e], __float_as_int(x));
}

// ---------------- edge gather ------------------------------------------------
__global__ void __launch_bounds__(256) k_gather(const float* __restrict__ tab) {
    int n = blockIdx.x * 8 + (threadIdx.x >> 5);
    int lane = threadIdx.x & 31;
    int beg = g_off[n], end = g_off[n + 1];
    float ax = 0.f, ay = 0.f, az = 0.f, aw = 0.f;
    int c4 = lane << 2;
    int i = beg;
    for (; i + 1 < end; i += 2) {
        int2 pA = g_pk[i];
        int2 pB = g_pk[i + 1];
        float xA = __int_as_float(pA.y);
        float xB = __int_as_float(pB.y);
        int iA = min((int)xA, TT - 2);
        int iB = min((int)xB, TT - 2);
        float wA = xA - (float)iA;
        float wB = xB - (float)iB;
        const float4 a0 = *(const float4*)&tab[(size_t)iA * FF + c4];
        const float4 a1 = *(const float4*)&tab[(size_t)(iA + 1) * FF + c4];
        const float4 b0 = *(const float4*)&tab[(size_t)iB * FF + c4];
        const float4 b1 = *(const float4*)&tab[(size_t)(iB + 1) * FF + c4];
        const float4 ta = *(const float4*)&g_t[(size_t)pA.x * DD + c4];
        const float4 tb = *(const float4*)&g_t[(size_t)pB.x * DD + c4];
        ax = fmaf(fmaf(wA, a1.x - a0.x, a0.x), ta.x, ax);
        ay = fmaf(fmaf(wA, a1.y - a0.y, a0.y), ta.y, ay);
        az = fmaf(fmaf(wA, a1.z - a0.z, a0.z), ta.z, az);
        aw = fmaf(fmaf(wA, a1.w - a0.w, a0.w), ta.w, aw);
        ax = fmaf(fmaf(wB, b1.x - b0.x, b0.x), tb.x, ax);
        ay = fmaf(fmaf(wB, b1.y - b0.y, b0.y), tb.y, ay);
        az = fmaf(fmaf(wB, b1.z - b0.z, b0.z), tb.z, az);
        aw = fmaf(fmaf(wB, b1.w - b0.w, b0.w), tb.w, aw);
    }
    if (i < end) {
        int2 pA = g_pk[i];
        float xA = __int_as_float(pA.y);
        int iA = min((int)xA, TT - 2);
        float wA = xA - (float)iA;
        const float4 a0 = *(const float4*)&tab[(size_t)iA * FF + c4];
        const float4 a1 = *(const float4*)&tab[(size_t)(iA + 1) * FF + c4];
        const float4 ta = *(const float4*)&g_t[(size_t)pA.x * DD + c4];
        ax = fmaf(fmaf(wA, a1.x - a0.x, a0.x), ta.x, ax);
        ay = fmaf(fmaf(wA, a1.y - a0.y, a0.y), ta.y, ay);
        az = fmaf(fmaf(wA, a1.z - a0.z, a0.z), ta.z, az);
        aw = fmaf(fmaf(wA, a1.w - a0.w, a0.w), ta.w, aw);
    }
    float4 o; o.x = ax; o.y = ay; o.z = az; o.w = aw;
    *(float4*)&g_agg[(size_t)n * DD + c4] = o;
}

// ---------------- bf16x3 stage GEMM, pre-split operands -----------------------
template <int BN, int K>
__device__ __forceinline__ void stage_gemm(
    const unsigned* __restrict__ Ah, const unsigned* __restrict__ Al,
    const unsigned* __restrict__ Bgh, const unsigned* __restrict__ Bgl,
    unsigned* __restrict__ Bsh, unsigned* __restrict__ Bsl,
    int tid, float (&acc)[2][BN / 32][4]) {
    constexpr int K2 = K / 2;
    constexpr int APK = K2 + 4;
    constexpr int BST = 20;
    constexpr int NCH = K / 32;
    constexpr int WN = BN / 4;
    constexpr int NT = BN / 32;
    int wid = tid >> 5, lane = tid & 31;
    int wm = wid & 1, wn = wid >> 1;
    int grp = lane >> 2, t4 = lane & 3;

    auto ldchunk = [&](int c, int buf) {
        constexpr int OPS = BN * 4;
#pragma unroll
        for (int it = 0; it < (2 * OPS) / 256; it++) {
            int idx = tid + it * 256;
            int comp = idx >= OPS;
            int j = comp ? idx - OPS : idx;
            int n = j >> 2, q = j & 3;
            const unsigned* gsrc = (comp ? Bgl : Bgh) + n * K2 + c * 16 + q * 4;
            unsigned* sdst = (comp ? Bsl : Bsh) + (buf * BN + n) * BST + q * 4;
            unsigned sa = (unsigned)__cvta_generic_to_shared(sdst);
            asm volatile("cp.async.cg.shared.global [%0], [%1], 16;" :: "r"(sa), "l"(gsrc));
        }
        asm volatile("cp.async.commit_group;");
    };

    ldchunk(0, 0);
    asm volatile("cp.async.wait_group 0;");
    __syncthreads();

#pragma unroll
    for (int im = 0; im < 2; im++)
#pragma unroll
        for (int in = 0; in < NT; in++)
#pragma unroll
            for (int q = 0; q < 4; q++) acc[im][in][q] = 0.0f;

    for (int c = 0; c < NCH; c++) {
        int buf = c & 1;
        if (c + 1 < NCH) ldchunk(c + 1, buf ^ 1);
#pragma unroll
        for (int kk = 0; kk < 2; kk++) {
            int ka = c * 16 + kk * 8;
            int kb = kk * 8;
            unsigned ah[2][4], al[2][4];
#pragma unroll
            for (int im = 0; im < 2; im++) {
                int rb = wm * 32 + im * 16 + grp;
                ah[im][0] = Ah[rb * APK + ka + t4];
                ah[im][1] = Ah[(rb + 8) * APK + ka + t4];
                ah[im][2] = Ah[rb * APK + ka + t4 + 4];
                ah[im][3] = Ah[(rb + 8) * APK + ka + t4 + 4];
                al[im][0] = Al[rb * APK + ka + t4];
                al[im][1] = Al[(rb + 8) * APK + ka + t4];
                al[im][2] = Al[rb * APK + ka + t4 + 4];
                al[im][3] = Al[(rb + 8) * APK + ka + t4 + 4];
            }
            unsigned bh[NT][2], bl[NT][2];
#pragma unroll
            for (int in = 0; in < NT; in++) {
                int nb = wn * WN + in * 8 + grp;
                int o = (buf * BN + nb) * BST + kb + t4;
                bh[in][0] = Bsh[o]; bh[in][1] = Bsh[o + 4];
                bl[in][0] = Bsl[o]; bl[in][1] = Bsl[o + 4];
            }
#pragma unroll
            for (int im = 0; im < 2; im++)
#pragma unroll
                for (int in = 0; in < NT; in++) {
                    float* d = acc[im][in];
                    MMA_BF16(d, al[im], bh[in]);
                    MMA_BF16(d, ah[im], bl[in]);
                    MMA_BF16(d, ah[im], bh[in]);
                }
        }
        if (c + 1 < NCH) {
            asm volatile("cp.async.wait_group 0;");
            __syncthreads();
        }
    }
}

// ---------------- fused layer kernel -----------------------------------------
template <int BN3, bool SSP3>
__global__ void __launch_bounds__(256)
k_layer(const unsigned* __restrict__ cf2h, const unsigned* __restrict__ cf2l,
        const float* __restrict__ cf2b,
        const unsigned* __restrict__ ilh, const unsigned* __restrict__ ill,
        const float* __restrict__ ilb,
        const unsigned* __restrict__ W3h, const unsigned* __restrict__ W3l,
        const float* __restrict__ b3, float* __restrict__ out3) {
    constexpr int APK = 68;
    extern __shared__ unsigned smu[];
    unsigned* A0h = smu;
    unsigned* A0l = smu + 4352;
    unsigned* A1h = smu + 8704;
    unsigned* A1l = smu + 13056;
    unsigned* Bsh = smu + 17408;
    unsigned* Bsl = smu + 22528;

    int tid = threadIdx.x;
    int m0 = blockIdx.x * 64;
    int wid = tid >> 5, lane = tid & 31;
    int wm = wid & 1, wn = wid >> 1;
    int grp = lane >> 2, t4 = lane & 3;

    for (int idx = tid; idx < 64 * 64; idx += 256) {
        int r = idx >> 6, k2 = idx & 63;
        float2 p = *(const float2*)&g_agg[(size_t)(m0 + r) * DD + 2 * k2];
        unsigned h, l_;
        split2(p.x, p.y, h, l_);
        A0h[r * APK + k2] = h;
        A0l[r * APK + k2] = l_;
    }

    float acc[2][4][4];

    stage_gemm<128, 128>(A0h, A0l, cf2h, cf2l, Bsh, Bsl, tid, acc);
#pragma unroll
    for (int im = 0; im < 2; im++) {
        int rb = wm * 32 + im * 16 + grp;
#pragma unroll
        for (int in = 0; in < 4; in++) {
            int col = wn * 32 + in * 8 + 2 * t4;
            float b0 = cf2b[col], b1 = cf2b[col + 1];
#pragma unroll
            for (int hr = 0; hr < 2; hr++) {
                int r = rb + hr * 8;
                float vx = sspf(acc[im][in][hr * 2 + 0] + b0);
                float vy = sspf(acc[im][in][hr * 2 + 1] + b1);
                unsigned h, l_;
                split2(vx, vy, h, l_);
                A1h[r * APK + (col >> 1)] = h;
                A1l[r * APK + (col >> 1)] = l_;
            }
        }
    }
    __syncthreads();

    stage_gemm<128, 128>(A1h, A1l, ilh, ill, Bsh, Bsl, tid, acc);
#pragma unroll
    for (int im = 0; im < 2; im++) {
        int rb = wm * 32 + im * 16 + grp;
#pragma unroll
        for (int in = 0; in < 4; in++) {
            int col = wn * 32 + in * 8 + 2 * t4;
            float b0 = ilb[col], b1 = ilb[col + 1];
#pragma unroll
            for (int hr = 0; hr < 2; hr++) {
                int r = rb + hr * 8;
                float* hp = &g_h[(size_t)(m0 + r) * DD + col];
                float2 hv = *(const float2*)hp;
                float2 v;
                v.x = acc[im][in][hr * 2 + 0] + b0 + hv.x;
                v.y = acc[im][in][hr * 2 + 1] + b1 + hv.y;
                *(float2*)hp = v;
                unsigned h, l_;
                split2(v.x, v.y, h, l_);
                A0h[r * APK + (col >> 1)] = h;
                A0l[r * APK + (col >> 1)] = l_;
            }
        }
    }
    __syncthreads();

    float acc3[2][BN3 / 32][4];
    stage_gemm<BN3, 128>(A0h, A0l, W3h, W3l, Bsh, Bsl, tid, acc3);
    constexpr int WN3 = BN3 / 4;
#pragma unroll
    for (int im = 0; im < 2; im++) {
        int rb = wm * 32 + im * 16 + grp;
#pragma unroll
        for (int in = 0; in < BN3 / 32; in++) {
            int col = wn * WN3 + in * 8 + 2 * t4;
            float b0 = b3[col], b1 = b3[col + 1];
#pragma unroll
            for (int hr = 0; hr < 2; hr++) {
                int r = m0 + rb + hr * 8;
                float x0 = acc3[im][in][hr * 2 + 0] + b0;
                float x1 = acc3[im][in][hr * 2 + 1] + b1;
                if (SSP3) { x0 = sspf(x0); x1 = sspf(x1); }
                float2 v; v.x = x0; v.y = x1;
                *(float2*)&out3[(size_t)r * BN3 + col] = v;
            }
        }
    }
}

// ---------------- standalone GEMM (tables + t0) --------------------------------
template <int BN, int K, int EPI>
__global__ void __launch_bounds__(256)
k_gemm3(const float* __restrict__ A,
        const unsigned* __restrict__ Bh, const unsigned* __restrict__ Bl,
        const float* __restrict__ bias, const float* __restrict__ scale,
        float* __restrict__ C, int sA, int sB, int sBias, int sC) {
    constexpr int K2 = K / 2;
    constexpr int APK = K2 + 4;
    extern __shared__ unsigned smu[];
    unsigned* Ah = smu;
    unsigned* Al = smu + 64 * APK;
    unsigned* Bsh = smu + 2 * 64 * APK;
    unsigned* Bsl = Bsh + 5120;

    A += (size_t)blockIdx.y * sA;
    Bh += (size_t)blockIdx.y * sB;
    Bl += (size_t)blockIdx.y * sB;
    if (bias) bias += (size_t)blockIdx.y * sBias;
    C += (size_t)blockIdx.y * sC;

    int tid = threadIdx.x;
    int m0 = blockIdx.x * 64;
    int wid = tid >> 5, lane = tid & 31;
    int wm = wid & 1, wn = wid >> 1;
    int grp = lane >> 2, t4 = lane & 3;

    for (int idx = tid; idx < 64 * K2; idx += 256) {
        int r = idx / K2, k2 = idx % K2;
        float2 p = *(const float2*)&A[(size_t)(m0 + r) * K + 2 * k2];
        unsigned h, l_;
        split2(p.x, p.y, h, l_);
        Ah[r * APK + k2] = h;
        Al[r * APK + k2] = l_;
    }

    float acc[2][BN / 32][4];
    stage_gemm<BN, K>(Ah, Al, Bh, Bl, Bsh, Bsl, tid, acc);

    constexpr int WN = BN / 4;
#pragma unroll
    for (int im = 0; im < 2; im++) {
        int rbase = m0 + wm * 32 + im * 16 + grp;
#pragma unroll
        for (int in = 0; in < BN / 32; in++) {
            int col = wn * WN + in * 8 + 2 * t4;
            float b0 = bias ? bias[col] : 0.f;
            float b1 = bias ? bias[col + 1] : 0.f;
#pragma unroll
            for (int hr = 0; hr < 2; hr++) {
                int r = rbase + hr * 8;
                float x0 = acc[im][in][hr * 2 + 0] + b0;
                float x1 = acc[im][in][hr * 2 + 1] + b1;
                if (EPI == 1) { x0 = sspf(x0); x1 = sspf(x1); }
                if (EPI == 2) { float sc = scale[r]; x0 *= sc; x1 *= sc; }
                float2 v; v.x = x0; v.y = x1;
                *(float2*)&C[(size_t)r * BN + col] = v;
            }
        }
    }
}

// ---------------- readout ----------------------------------------------------
__global__ void k_readout(const int* __restrict__ batch, const float* __restrict__ w,
                          const float* __restrict__ b, float* __restrict__ out) {
    int gw = (blockIdx.x * blockDim.x + threadIdx.x) >> 5;
    int lane = threadIdx.x & 31;
    if (gw >= NA) return;
    float v = g_r[gw * 64 + lane] * w[lane] + g_r[gw * 64 + lane + 32] * w[lane + 32];
#pragma unroll
    for (int o = 16; o > 0; o >>= 1) v += __shfl_down_sync(0xFFFFFFFFu, v, o);
    if (lane == 0) atomicAdd(&out[batch[gw]], v + b[0]);
}

// ---------------- launch -----------------------------------------------------
extern "C" void kernel_launch(void* const* d_in, const int* in_sizes, int n_in,
                              void* d_out, int out_size) {
    const float* z    = (const float*)d_in[0];
    const float* pos  = (const float*)d_in[1];
    const int*   bat  = (const int*)d_in[2];
    const int*   esrc = (const int*)d_in[3];
    const int*   edst = (const int*)d_in[4];
    const float* embW = (const float*)d_in[5];
    const float* embB = (const float*)d_in[6];
    const float* W1   = (const float*)d_in[7];
    const float* b1   = (const float*)d_in[8];
    const float* W2   = (const float*)d_in[9];
    const float* b2   = (const float*)d_in[10];
    const float* cf1  = (const float*)d_in[11];
    const float* cf2  = (const float*)d_in[12];
    const float* cf2b = (const float*)d_in[13];
    const float* ilW  = (const float*)d_in[14];
    const float* ilb  = (const float*)d_in[15];
    const float* l1W  = (const float*)d_in[16];
    const float* l1b  = (const float*)d_in[17];
    const float* l2W  = (const float*)d_in[18];
    const float* l2b  = (const float*)d_in[19];
    float* out = (float*)d_out;

    float *p_h, *p_t, *p_r, *p_R, *p_Cd, *p_ttmp, *p_tab, *p_zero;
    unsigned *p_Wh, *p_Wl;
    int *p_cnt;
    cudaGetSymbolAddress((void**)&p_h, g_h);
    cudaGetSymbolAddress((void**)&p_t, g_t);
    cudaGetSymbolAddress((void**)&p_r, g_r);
    cudaGetSymbolAddress((void**)&p_R, g_R);
    cudaGetSymbolAddress((void**)&p_Cd, g_Cd);
    cudaGetSymbolAddress((void**)&p_ttmp, g_ttmp);
    cudaGetSymbolAddress((void**)&p_tab, g_tab);
    cudaGetSymbolAddress((void**)&p_zero, g_zero);
    cudaGetSymbolAddress((void**)&p_Wh, g_Wh);
    cudaGetSymbolAddress((void**)&p_Wl, g_Wl);
    cudaGetSymbolAddress((void**)&p_cnt, g_cnt);

    const int SM_G128 = 75776, SM_G64 = 59392, SM_L = 110592;
    cudaFuncSetAttribute((const void*)k_gemm3<128, 128, 0>,
                         cudaFuncAttributeMaxDynamicSharedMemorySize, SM_G128);
    cudaFuncSetAttribute((const void*)k_gemm3<128, 128, 2>,
                         cudaFuncAttributeMaxDynamicSharedMemorySize, SM_G128);
    cudaFuncSetAttribute((const void*)k_gemm3<128, 64, 1>,
                         cudaFuncAttributeMaxDynamicSharedMemorySize, SM_G64);
    cudaFuncSetAttribute((const void*)k_layer<128, false>,
                         cudaFuncAttributeMaxDynamicSharedMemorySize, SM_L);
    cudaFuncSetAttribute((const void*)k_layer<64, true>,
                         cudaFuncAttributeMaxDynamicSharedMemorySize, SM_L);

    cudaMemsetAsync(p_cnt, 0, NA * sizeof(int));
    k_prep<<<NA * DD / 256, 256>>>(z, embW, embB, pos, esrc, edst, W1);
    k_split<<<(TOTW + 255) / 256, 256>>>(W2, cf1, cf2, ilW, l1W);
    k_scan<<<1, 1024>>>(out);
    k_fill<<<NE / 256, 256>>>(esrc, edst);

    {
        dim3 g1(TT / 64, NL);
        k_gemm3<128, 64, 1><<<g1, 256, SM_G64>>>(
            p_R, p_Wh + OFF_W1, p_Wl + OFF_W1, b1, nullptr, p_ttmp,
            0, 4096, FF, TT * FF);
        k_gemm3<128, 128, 2><<<g1, 256, SM_G128>>>(
            p_ttmp, p_Wh + OFF_W2, p_Wl + OFF_W2, b2, p_Cd, p_tab,
            TT * FF, 8192, FF, TT * FF);
    }

    k_gemm3<128, 128, 0><<<NA / 64, 256, SM_G128>>>(
        p_h, p_Wh + OFF_CF1, p_Wl + OFF_CF1, nullptr, nullptr, p_t, 0, 0, 0, 0);

    for (int l = 0; l < NL; l++) {
        k_gather<<<NA / 8, 256>>>(p_tab + (size_t)l * TT * FF);
        if (l < NL - 1) {
            k_layer<128, false><<<NA / 64, 256, SM_L>>>(
                p_Wh + OFF_CF2 + l * 8192, p_Wl + OFF_CF2 + l * 8192,
                cf2b + (size_t)l * DD,
                p_Wh + OFF_IL + l * 8192, p_Wl + OFF_IL + l * 8192,
                ilb + (size_t)l * DD,
                p_Wh + OFF_CF1 + (l + 1) * 8192, p_Wl + OFF_CF1 + (l + 1) * 8192,
                p_zero, p_t);
        } else {
            k_layer<64, true><<<NA / 64, 256, SM_L>>>(
                p_Wh + OFF_CF2 + l * 8192, p_Wl + OFF_CF2 + l * 8192,
                cf2b + (size_t)l * DD,
                p_Wh + OFF_IL + l * 8192, p_Wl + OFF_IL + l * 8192,
                ilb + (size_t)l * DD,
                p_Wh + OFF_L1, p_Wl + OFF_L1, l1b, p_r);
        }
    }

    k_readout<<<(NA * 32 + 255) / 256, 256>>>(bat, l2W, l2b, out);
}